// round 15
// baseline (speedup 1.0000x reference)
#include <cuda_runtime.h>
#include <cuda_bf16.h>
#include <math.h>
#include <stdint.h>

// Problem constants (B=2, S=8192 -> T=16384), H=1024, F=2048, E=8, K=2
#define Tt    16384
#define Hd    1024
#define Fd    2048
#define NE    8
#define NSLOT 32768          // T * K
#define CAP   5120           // ceil(1.25 * T * K / E) -- exactly 40 * 128

// ---------------- static device scratch (~873 MB total) ----------------------
#define XN4 (NE * CAP * Hd / 8)   // uint4 count (8 bf16 each)
#define HN4 (NE * CAP * Fd / 8)
#define WN4 (NE * Hd * Fd / 8)
__device__ uint4 g_xhi4[XN4];              // dispatched x, bf16 hi plane
__device__ uint4 g_xlo4[XN4];              // dispatched x, bf16 lo plane
__device__ uint4 g_hhi4[HN4];              // h hi plane
__device__ uint4 g_hlo4[HN4];              // h lo plane
__device__ uint4 g_wghi4[WN4];             // Wg planes [E][H][F]
__device__ uint4 g_wglo4[WN4];
__device__ uint4 g_wuhi4[WN4];             // Wu planes [E][H][F]
__device__ uint4 g_wulo4[WN4];
__device__ uint4 g_w2hi4[WN4];             // W2 planes [E][F][H]
__device__ uint4 g_w2lo4[WN4];
__device__ float g_y[NE * CAP * Hd];
__device__ unsigned long long g_keys[NE * NSLOT];
__device__ int   g_cnt[NE];
__device__ int   g_active[NE];
__device__ float g_imp[NE];
__device__ int   g_load[NE];
__device__ int   g_fe[NSLOT];
__device__ float g_fp[NSLOT];
__device__ int   g_pos[NSLOT];
__device__ float g_w[NSLOT];

// ---------------- truncation split: exact, packs 2 elems -------------------
__device__ __forceinline__ void split2(float x, float y, uint32_t& hi, uint32_t& lo) {
    uint32_t ux = __float_as_uint(x);
    uint32_t uy = __float_as_uint(y);
    hi = __byte_perm(ux, uy, 0x7632);
    float lx = x - __uint_as_float(ux & 0xFFFF0000u);
    float ly = y - __uint_as_float(uy & 0xFFFF0000u);
    asm("cvt.rn.bf16x2.f32 %0, %1, %2;" : "=r"(lo) : "f"(ly), "f"(lx));
}

// ---------------- per-launch counter reset ---------------------------------
__global__ void zero_kernel() {
    int i = threadIdx.x;
    if (i < NE) { g_cnt[i] = 0; g_imp[i] = 0.f; g_load[i] = 0; }
}

// ---------------- router ----------------------------------------------------
__global__ void router_kernel(const float* __restrict__ x,
                              const float* __restrict__ Wr) {
    __shared__ float sWr[Hd * NE];
    __shared__ float s_imp[NE];
    __shared__ int   s_load[NE];
    int tid = threadIdx.x;
    if (tid < NE) { s_imp[tid] = 0.f; s_load[tid] = 0; }
    for (int i = tid; i < Hd * NE / 4; i += 256)
        ((float4*)sWr)[i] = ((const float4*)Wr)[i];
    __syncthreads();

    int warp = tid >> 5, lane = tid & 31;
    int t = blockIdx.x * 8 + warp;

    float acc[NE];
#pragma unroll
    for (int e = 0; e < NE; e++) acc[e] = 0.f;

    const float* xr = x + (size_t)t * Hd;
    for (int j = lane; j < Hd; j += 32) {
        float xv = xr[j];
#pragma unroll
        for (int e = 0; e < NE; e++) acc[e] += xv * sWr[j * NE + e];
    }
#pragma unroll
    for (int o = 16; o; o >>= 1)
#pragma unroll
        for (int e = 0; e < NE; e++)
            acc[e] += __shfl_xor_sync(0xffffffffu, acc[e], o);

    if (lane == 0) {
        float mx = acc[0];
#pragma unroll
        for (int e = 1; e < NE; e++) mx = fmaxf(mx, acc[e]);
        float pe[NE], s = 0.f;
#pragma unroll
        for (int e = 0; e < NE; e++) { pe[e] = expf(acc[e] - mx); s += pe[e]; }
        float inv = 1.f / s;
#pragma unroll
        for (int e = 0; e < NE; e++) { pe[e] *= inv; atomicAdd(&s_imp[e], pe[e]); }
        int e0 = 0;
#pragma unroll
        for (int e = 1; e < NE; e++) if (pe[e] > pe[e0]) e0 = e;
        int e1 = (e0 == 0) ? 1 : 0;
#pragma unroll
        for (int e = 0; e < NE; e++)
            if (e != e0 && e != e1 && pe[e] > pe[e1]) e1 = e;
        atomicAdd(&s_load[e0], 1);
        atomicAdd(&s_load[e1], 1);
        float ps = pe[e0] + pe[e1];
        g_fe[2 * t]     = e0;
        g_fe[2 * t + 1] = e1;
        g_fp[2 * t]     = pe[e0] / ps;
        g_fp[2 * t + 1] = pe[e1] / ps;
    }
    __syncthreads();
    if (tid < NE) {
        atomicAdd(&g_imp[tid], s_imp[tid]);
        atomicAdd(&g_load[tid], s_load[tid]);
    }
}

// ---------------- group slots by expert: packed keys -------------------------
__global__ void build_lists() {
    int n = blockIdx.x * 256 + threadIdx.x;
    if (n >= NSLOT) return;
    int e = g_fe[n];
    int i = atomicAdd(&g_cnt[e], 1);
    unsigned long long key =
        ((unsigned long long)__float_as_uint(g_fp[n]) << 32) |
        (unsigned int)(NSLOT - 1 - n);
    g_keys[e * NSLOT + i] = key;
}

__global__ void finalize_kernel() {
    int e = threadIdx.x;
    if (e < NE) g_active[e] = min(g_cnt[e], CAP);
}

// ---------------- rank: smem-tiled exact descending rank ---------------------
__global__ void rank_kernel() {
    int e = blockIdx.y;
    int c = g_cnt[e];
    int base = blockIdx.x * 256;
    if (base >= c) return;
    __shared__ unsigned long long sk[512];
    int tid = threadIdx.x;
    int idx = base + tid;
    bool act = idx < c;
    unsigned long long key = 0;
    if (act) key = g_keys[e * NSLOT + idx];
    int r = 0;
    for (int chunk = 0; chunk < c; chunk += 512) {
        int m = min(512, c - chunk);
        for (int i = tid; i < m; i += 256)
            sk[i] = g_keys[e * NSLOT + chunk + i];
        __syncthreads();
        if (act)
            for (int i = 0; i < m; i++)
                if (sk[i] > key) r++;
        __syncthreads();
    }
    if (act) {
        int n = NSLOT - 1 - (int)(unsigned int)(key & 0xFFFFFFFFu);
        float p = __uint_as_float((unsigned int)(key >> 32));
        bool keep = r < CAP;
        g_pos[n] = keep ? r : (CAP - 1);
        g_w[n]   = keep ? p : 0.f;
    }
}

// ---------------- dispatch: gather + split x into bf16 hi/lo planes ----------
__global__ void scatter_kernel(const float* __restrict__ x) {
    int n = blockIdx.x;
    float w = g_w[n];
    if (w == 0.f) return;
    int e = g_fe[n], pos = g_pos[n];
    int t = n >> 1;
    const float4* src = (const float4*)(x + (size_t)t * Hd);
    int tid = threadIdx.x;
    float4 a = src[2 * tid], b = src[2 * tid + 1];
    uint32_t h0, l0, h1, l1, h2, l2, h3, l3;
    split2(a.x, a.y, h0, l0);
    split2(a.z, a.w, h1, l1);
    split2(b.x, b.y, h2, l2);
    split2(b.z, b.w, h3, l3);
    size_t ub = ((size_t)e * CAP + pos) * (Hd / 8) + tid;
    g_xhi4[ub] = make_uint4(h0, h1, h2, h3);
    g_xlo4[ub] = make_uint4(l0, l1, l2, l3);
}

// ---------------- weight split: destinations resolved IN DEVICE CODE ---------
__global__ void wsplit_kernel(const float* __restrict__ W, int which) {
    uint4* hi;
    uint4* lo;
    if (which == 0)      { hi = g_wghi4; lo = g_wglo4; }
    else if (which == 1) { hi = g_wuhi4; lo = g_wulo4; }
    else                 { hi = g_w2hi4; lo = g_w2lo4; }
    size_t idx = (size_t)blockIdx.x * 256 + threadIdx.x;
    const float4* Wv = (const float4*)W;
    float4 a = Wv[2 * idx], b = Wv[2 * idx + 1];
    uint32_t h0, l0, h1, l1, h2, l2, h3, l3;
    split2(a.x, a.y, h0, l0);
    split2(a.z, a.w, h1, l1);
    split2(b.x, b.y, h2, l2);
    split2(b.z, b.w, h3, l3);
    hi[idx] = make_uint4(h0, h1, h2, h3);
    lo[idx] = make_uint4(l0, l1, l2, l3);
}

// ================= bf16x3 tensor-core grouped GEMM ===========================
// Round-9 proven compute shape: block 128x128x32, 8 warps (4x2), warp tile
// 32x64, two barriers per k-tile, acc += hh + hl + lh.
// ALL operands are pre-split bf16 hi/lo planes; tile staging is a cp.async
// double-buffer pipeline (8 x 16B per thread per tile, one commit group,
// wait_group 1).

#define SA_STRIDE 40
#define SB_STRIDE 136
#define A_BYTES   10240   // 128 * 80
#define B_BYTES   8704    // 32 * 272
#define BUF_BYTES 37888
#define SMEM_GEMM 75776

__device__ __forceinline__ void cp16(uint32_t dst, const void* src) {
    asm volatile("cp.async.cg.shared.global [%0], [%1], 16;" :: "r"(dst), "l"(src));
}
__device__ __forceinline__ void ldsm4(uint32_t* r, uint32_t addr) {
    asm volatile("ldmatrix.sync.aligned.m8n8.x4.shared.b16 {%0,%1,%2,%3}, [%4];"
        : "=r"(r[0]), "=r"(r[1]), "=r"(r[2]), "=r"(r[3]) : "r"(addr));
}
__device__ __forceinline__ void ldsm4t(uint32_t* r, uint32_t addr) {
    asm volatile("ldmatrix.sync.aligned.m8n8.x4.trans.shared.b16 {%0,%1,%2,%3}, [%4];"
        : "=r"(r[0]), "=r"(r[1]), "=r"(r[2]), "=r"(r[3]) : "r"(addr));
}
__device__ __forceinline__ void mma16816(float* d, const uint32_t* a, uint32_t b0, uint32_t b1) {
    asm volatile("mma.sync.aligned.m16n8k16.row.col.f32.bf16.bf16.f32 "
        "{%0,%1,%2,%3}, {%4,%5,%6,%7}, {%8,%9}, {%0,%1,%2,%3};"
        : "+f"(d[0]), "+f"(d[1]), "+f"(d[2]), "+f"(d[3])
        : "r"(a[0]), "r"(a[1]), "r"(a[2]), "r"(a[3]), "r"(b0), "r"(b1));
}

// issue one k-tile's loads into buffer at smem addr sb_ and advance pointers
#define ISSUE_CP(sb_) do {                                                     \
    cp16((sb_) + offA,                Agh);                                    \
    cp16((sb_) + offA + 16,           Agh + 8);                                \
    cp16((sb_) + A_BYTES + offA,      Agl);                                    \
    cp16((sb_) + A_BYTES + offA + 16, Agl + 8);                                \
    cp16((sb_) + 2 * A_BYTES + offB,                Bgh);                      \
    cp16((sb_) + 2 * A_BYTES + offB + 16,           Bgh + 8);                  \
    cp16((sb_) + 2 * A_BYTES + B_BYTES + offB,      Bgl);                      \
    cp16((sb_) + 2 * A_BYTES + B_BYTES + offB + 16, Bgl + 8);                  \
    asm volatile("cp.async.commit_group;");                                    \
    Agh += 32; Agl += 32;                                                      \
    Bgh += (size_t)32 * NW; Bgl += (size_t)32 * NW;                            \
} while (0)

// ---- FUSED gate+up GEMM ------------------------------------------------------
__global__ __launch_bounds__(256, 1) void mma_fused() {
    const int K = Hd, NW = Fd;
    int e = blockIdx.z;
    int row0 = blockIdx.y * 128;
    if (row0 >= g_active[e]) return;
    int col0 = blockIdx.x * 64;

    extern __shared__ char smem[];
    uint32_t sbase = (uint32_t)__cvta_generic_to_shared(smem);

    int tid  = threadIdx.x;
    int lane = tid & 31, wid = tid >> 5;
    int wm = wid >> 1, wn = wid & 1;

    int arow = tid >> 1, acol = (tid & 1) * 16;
    int brow = tid >> 3, bsub = tid & 7;
    int bcol = bsub * 16;
    int gcol = col0 + (bcol & 63);

    const __nv_bfloat16* Agh = (const __nv_bfloat16*)g_xhi4
        + ((size_t)e * CAP + row0 + arow) * K + acol;
    const __nv_bfloat16* Agl = (const __nv_bfloat16*)g_xlo4
        + ((size_t)e * CAP + row0 + arow) * K + acol;
    const __nv_bfloat16* Bgh = (const __nv_bfloat16*)(bsub < 4 ? g_wghi4 : g_wuhi4)
        + (size_t)e * K * NW + (size_t)brow * NW + gcol;
    const __nv_bfloat16* Bgl = (const __nv_bfloat16*)(bsub < 4 ? g_wglo4 : g_wulo4)
        + (size_t)e * K * NW + (size_t)brow * NW + gcol;

    int offA = arow * 80 + acol * 2;
    int offB = brow * 272 + bcol * 2;

    float acc[2][8][4];
#pragma unroll
    for (int mi = 0; mi < 2; mi++)
#pragma unroll
        for (int ni = 0; ni < 8; ni++)
#pragma unroll
            for (int k = 0; k < 4; k++) acc[mi][ni][k] = 0.f;

    int kTiles = K >> 5;
    ISSUE_CP(sbase);   // tile 0 -> buf 0

    for (int kt = 0; kt < kTiles; ++kt) {
        int cur = kt & 1;
        if (kt + 1 < kTiles) {
            ISSUE_CP(sbase + (cur ^ 1) * BUF_BYTES);
            asm volatile("cp.async.wait_group 1;" ::: "memory");
        } else {
            asm volatile("cp.async.wait_group 0;" ::: "memory");
        }
        __syncthreads();

        uint32_t sA = sbase + cur * BUF_BYTES;
        uint32_t sB = sA + 2 * A_BYTES;
#pragma unroll
        for (int ks = 0; ks < 2; ks++) {
            uint32_t ah[2][4], al[2][4], bh[4][4], bl[4][4];
#pragma unroll
            for (int mi = 0; mi < 2; mi++) {
                uint32_t r = wm * 32 + mi * 16 + (lane & 15);
                uint32_t c = ks * 16 + ((lane >> 4) << 3);
                uint32_t addr = sA + (r * SA_STRIDE + c) * 2;
                ldsm4(ah[mi], addr);
                ldsm4(al[mi], addr + A_BYTES);
            }
#pragma unroll
            for (int nb = 0; nb < 4; nb++) {
                uint32_t r = ks * 16 + (lane & 15);
                uint32_t c = wn * 64 + nb * 16 + ((lane >> 4) << 3);
                uint32_t addr = sB + (r * SB_STRIDE + c) * 2;
                ldsm4t(bh[nb], addr);
                ldsm4t(bl[nb], addr + B_BYTES);
            }
#pragma unroll
            for (int mi = 0; mi < 2; mi++)
#pragma unroll
                for (int nb = 0; nb < 4; nb++)
#pragma unroll
                    for (int j = 0; j < 2; j++) {
                        int ni = nb * 2 + j;
                        mma16816(acc[mi][ni], ah[mi], bh[nb][2 * j], bh[nb][2 * j + 1]);
                        mma16816(acc[mi][ni], ah[mi], bl[nb][2 * j], bl[nb][2 * j + 1]);
                        mma16816(acc[mi][ni], al[mi], bh[nb][2 * j], bh[nb][2 * j + 1]);
                    }
        }
        __syncthreads();
    }

    // ---- fused epilogue: up warps -> smem, gate warps compute h -> planes ----
    float* su = (float*)smem;
    int gq = lane >> 2, q = lane & 3;
    if (wn == 1) {
#pragma unroll
        for (int mi = 0; mi < 2; mi++) {
            int rl = wm * 32 + mi * 16 + gq;
#pragma unroll
            for (int ni = 0; ni < 8; ni++) {
                int c = ni * 8 + q * 2;
                su[rl * 64 + c]           = acc[mi][ni][0];
                su[rl * 64 + c + 1]       = acc[mi][ni][1];
                su[(rl + 8) * 64 + c]     = acc[mi][ni][2];
                su[(rl + 8) * 64 + c + 1] = acc[mi][ni][3];
            }
        }
    }
    __syncthreads();
    if (wn == 0) {
        __nv_bfloat16* HH = (__nv_bfloat16*)g_hhi4 + (size_t)e * CAP * Fd;
        __nv_bfloat16* HL = (__nv_bfloat16*)g_hlo4 + (size_t)e * CAP * Fd;
#pragma unroll
        for (int mi = 0; mi < 2; mi++) {
            int rl = wm * 32 + mi * 16 + gq;
#pragma unroll
            for (int ni = 0; ni < 8; ni++) {
                int c = ni * 8 + q * 2;
                float u00 = su[rl * 64 + c];
                float u01 = su[rl * 64 + c + 1];
                float u10 = su[(rl + 8) * 64 + c];
                float u11 = su[(rl + 8) * 64 + c + 1];
                float g00 = acc[mi][ni][0], g01 = acc[mi][ni][1];
                float g10 = acc[mi][ni][2], g11 = acc[mi][ni][3];
                float h00 = g00 / (1.f + expf(-g00)) * u00;
                float h01 = g01 / (1.f + expf(-g01)) * u01;
                float h10 = g10 / (1.f + expf(-g10)) * u10;
                float h11 = g11 / (1.f + expf(-g11)) * u11;
                uint32_t hp0, lp0, hp1, lp1;
                split2(h00, h01, hp0, lp0);
                split2(h10, h11, hp1, lp1);
                size_t i0 = (size_t)(row0 + rl) * Fd + col0 + c;
                size_t i1 = i0 + (size_t)8 * Fd;
                *(uint32_t*)&HH[i0] = hp0;
                *(uint32_t*)&HL[i0] = lp0;
                *(uint32_t*)&HH[i1] = hp1;
                *(uint32_t*)&HL[i1] = lp1;
            }
        }
    }
}

// ---- down GEMM: y = h @ W2, all pre-split planes, cp.async pipeline ---------
__global__ __launch_bounds__(256, 1) void mma_down() {
    const int K = Fd, NW = Hd;
    int e = blockIdx.z;
    int row0 = blockIdx.y * 128;
    if (row0 >= g_active[e]) return;
    int col0 = blockIdx.x * 128;

    extern __shared__ char smem[];
    uint32_t sbase = (uint32_t)__cvta_generic_to_shared(smem);

    int tid  = threadIdx.x;
    int lane = tid & 31, wid = tid >> 5;
    int wm = wid >> 1, wn = wid & 1;

    int arow = tid >> 1, acol = (tid & 1) * 16;
    int brow = tid >> 3, bcol = (tid & 7) * 16;

    const __nv_bfloat16* Agh = (const __nv_bfloat16*)g_hhi4
        + ((size_t)e * CAP + row0 + arow) * K + acol;
    const __nv_bfloat16* Agl = (const __nv_bfloat16*)g_hlo4
        + ((size_t)e * CAP + row0 + arow) * K + acol;
    const __nv_bfloat16* Bgh = (const __nv_bfloat16*)g_w2hi4
        + (size_t)e * K * NW + (size_t)brow * NW + col0 + bcol;
    const __nv_bfloat16* Bgl = (const __nv_bfloat16*)g_w2lo4
        + (size_t)e * K * NW + (size_t)brow * NW + col0 + bcol;

    int offA = arow * 80 + acol * 2;
    int offB = brow * 272 + bcol * 2;

    float acc[2][8][4];
#pragma unroll
    for (int mi = 0; mi < 2; mi++)
#pragma unroll
        for (int ni = 0; ni < 8; ni++)
#pragma unroll
            for (int k = 0; k < 4; k++) acc[mi][ni][k] = 0.f;

    int kTiles = K >> 5;
    ISSUE_CP(sbase);

    for (int kt = 0; kt < kTiles; ++kt) {
        int cur = kt & 1;
        if (kt + 1 < kTiles) {
            ISSUE_CP(sbase + (cur ^ 1) * BUF_BYTES);
            asm volatile("cp.async.wait_group 1;" ::: "memory");
        } else {
            asm volatile("cp.async.wait_group 0;" ::: "memory");
        }
        __syncthreads();

        uint32_t sA = sbase + cur * BUF_BYTES;
        uint32_t sB = sA + 2 * A_BYTES;
#pragma unroll
        for (int ks = 0; ks < 2; ks++) {
            uint32_t ah[2][4], al[2][4], bh[4][4], bl[4][4];
#pragma unroll
            for (int mi = 0; mi < 2; mi++) {
                uint32_t r = wm * 32 + mi * 16 + (lane & 15);
                uint32_t c = ks * 16 + ((lane >> 4) << 3);
                uint32_t addr = sA + (r * SA_STRIDE + c) * 2;
                ldsm4(ah[mi], addr);
                ldsm4(al[mi], addr + A_BYTES);
            }
#pragma unroll
            for (int nb = 0; nb < 4; nb++) {
                uint32_t r = ks * 16 + (lane & 15);
                uint32_t c = wn * 64 + nb * 16 + ((lane >> 4) << 3);
                uint32_t addr = sB + (r * SB_STRIDE + c) * 2;
                ldsm4t(bh[nb], addr);
                ldsm4t(bl[nb], addr + B_BYTES);
            }
#pragma unroll
            for (int mi = 0; mi < 2; mi++)
#pragma unroll
                for (int nb = 0; nb < 4; nb++)
#pragma unroll
                    for (int j = 0; j < 2; j++) {
                        int ni = nb * 2 + j;
                        mma16816(acc[mi][ni], ah[mi], bh[nb][2 * j], bh[nb][2 * j + 1]);
                        mma16816(acc[mi][ni], ah[mi], bl[nb][2 * j], bl[nb][2 * j + 1]);
                        mma16816(acc[mi][ni], al[mi], bh[nb][2 * j], bh[nb][2 * j + 1]);
                    }
        }
        __syncthreads();
    }

    float* C = g_y + (size_t)e * CAP * NW;
    int gq = lane >> 2, q = lane & 3;
#pragma unroll
    for (int mi = 0; mi < 2; mi++) {
        int r = row0 + wm * 32 + mi * 16 + gq;
#pragma unroll
        for (int ni = 0; ni < 8; ni++) {
            int c = col0 + wn * 64 + ni * 8 + q * 2;
            size_t i0 = (size_t)r * NW + c;
            size_t i1 = i0 + (size_t)8 * NW;
            *(float2*)&C[i0] = make_float2(acc[mi][ni][0], acc[mi][ni][1]);
            *(float2*)&C[i1] = make_float2(acc[mi][ni][2], acc[mi][ni][3]);
        }
    }
}

// ---------------- combine ----------------------------------------------------
__global__ void combine_kernel(float* __restrict__ out) {
    int t = blockIdx.x;
    int tid = threadIdx.x;
    int n0 = 2 * t, n1 = 2 * t + 1;
    float w0 = g_w[n0], w1 = g_w[n1];
    const float4* y0 = (const float4*)(g_y + ((size_t)g_fe[n0] * CAP + g_pos[n0]) * Hd);
    const float4* y1 = (const float4*)(g_y + ((size_t)g_fe[n1] * CAP + g_pos[n1]) * Hd);
    float4 a = y0[tid], b = y1[tid];
    float4 o;
    o.x = w0 * a.x + w1 * b.x;
    o.y = w0 * a.y + w1 * b.y;
    o.z = w0 * a.z + w1 * b.z;
    o.w = w0 * a.w + w1 * b.w;
    ((float4*)(out + (size_t)t * Hd))[tid] = o;
}

// ---------------- aux loss -----------------------------------------------------
__global__ void aux_kernel(float* __restrict__ out, int out_size) {
    if (threadIdx.x == 0) {
        float s = 0.f;
#pragma unroll
        for (int e = 0; e < NE; e++) s += g_imp[e] * (float)g_load[e];
        float aux = (float)NE * s / (float)(Tt * 2);
        if (out_size > Tt * Hd) out[(size_t)Tt * Hd] = aux;
    }
}

// ---------------- launch -------------------------------------------------------
extern "C" void kernel_launch(void* const* d_in, const int* in_sizes, int n_in,
                              void* d_out, int out_size) {
    const float* x  = (const float*)d_in[0];
    const float* Wr = (const float*)d_in[1];
    const float* Wg = (const float*)d_in[2];
    const float* Wu = (const float*)d_in[3];
    const float* W2 = (const float*)d_in[4];
    float* out = (float*)d_out;

    int smem_bytes = SMEM_GEMM;
    cudaFuncSetAttribute(mma_fused, cudaFuncAttributeMaxDynamicSharedMemorySize, smem_bytes);
    cudaFuncSetAttribute(mma_down,  cudaFuncAttributeMaxDynamicSharedMemorySize, smem_bytes);

    zero_kernel<<<1, 32>>>();
    router_kernel<<<Tt / 8, 256>>>(x, Wr);
    build_lists<<<NSLOT / 256, 256>>>();
    finalize_kernel<<<1, 32>>>();
    rank_kernel<<<dim3(NSLOT / 256, NE), 256>>>();
    scatter_kernel<<<NSLOT, 128>>>(x);

    int wblk = (NE * Hd * Fd) / (256 * 8);
    wsplit_kernel<<<wblk, 256>>>(Wg, 0);
    wsplit_kernel<<<wblk, 256>>>(Wu, 1);
    wsplit_kernel<<<wblk, 256>>>(W2, 2);

    dim3 grid_fused(Fd / 64, CAP / 128, NE);   // 32 x 40 x 8
    dim3 grid_down (Hd / 128, CAP / 128, NE);  //  8 x 40 x 8

    mma_fused<<<grid_fused, 256, smem_bytes>>>();  // h = silu(x@Wg)*(x@Wu)
    mma_down <<<grid_down, 256, smem_bytes>>>();   // y = h @ W2

    combine_kernel<<<Tt, 256>>>(out);
    aux_kernel<<<1, 32>>>(out, out_size);
}

// round 17
// speedup vs baseline: 1.0837x; 1.0837x over previous
#include <cuda_runtime.h>
#include <cuda_bf16.h>
#include <math.h>
#include <stdint.h>

// Problem constants (B=2, S=8192 -> T=16384), H=1024, F=2048, E=8, K=2
#define Tt    16384
#define Hd    1024
#define Fd    2048
#define NE    8
#define NSLOT 32768          // T * K
#define CAP   5120           // ceil(1.25 * T * K / E) -- exactly 40 * 128

// ---------------- static device scratch (~873 MB total) ----------------------
#define XN4 (NE * CAP * Hd / 8)   // uint4 count (8 bf16 each)
#define HN4 (NE * CAP * Fd / 8)
#define WN4 (NE * Hd * Fd / 8)
__device__ uint4 g_xhi4[XN4];              // dispatched x, bf16 hi plane
__device__ uint4 g_xlo4[XN4];              // dispatched x, bf16 lo plane
__device__ uint4 g_hhi4[HN4];              // h hi plane
__device__ uint4 g_hlo4[HN4];              // h lo plane
__device__ uint4 g_wghi4[WN4];             // Wg planes [E][H][F]
__device__ uint4 g_wglo4[WN4];
__device__ uint4 g_wuhi4[WN4];             // Wu planes [E][H][F]
__device__ uint4 g_wulo4[WN4];
__device__ uint4 g_w2hi4[WN4];             // W2 planes [E][F][H]
__device__ uint4 g_w2lo4[WN4];
__device__ float g_y[NE * CAP * Hd];
__device__ unsigned long long g_keys[NE * NSLOT];
__device__ int   g_cnt[NE];
__device__ int   g_active[NE];
__device__ float g_imp[NE];
__device__ int   g_load[NE];
__device__ int   g_fe[NSLOT];
__device__ float g_fp[NSLOT];
__device__ int   g_pos[NSLOT];
__device__ float g_w[NSLOT];

// ---------------- truncation split: exact, packs 2 elems -------------------
__device__ __forceinline__ void split2(float x, float y, uint32_t& hi, uint32_t& lo) {
    uint32_t ux = __float_as_uint(x);
    uint32_t uy = __float_as_uint(y);
    hi = __byte_perm(ux, uy, 0x7632);
    float lx = x - __uint_as_float(ux & 0xFFFF0000u);
    float ly = y - __uint_as_float(uy & 0xFFFF0000u);
    asm("cvt.rn.bf16x2.f32 %0, %1, %2;" : "=r"(lo) : "f"(ly), "f"(lx));
}

// ---------------- per-launch counter reset ---------------------------------
__global__ void zero_kernel() {
    int i = threadIdx.x;
    if (i < NE) { g_cnt[i] = 0; g_imp[i] = 0.f; g_load[i] = 0; }
}

// ---------------- router ----------------------------------------------------
__global__ void router_kernel(const float* __restrict__ x,
                              const float* __restrict__ Wr) {
    __shared__ float sWr[Hd * NE];
    __shared__ float s_imp[NE];
    __shared__ int   s_load[NE];
    int tid = threadIdx.x;
    if (tid < NE) { s_imp[tid] = 0.f; s_load[tid] = 0; }
    for (int i = tid; i < Hd * NE / 4; i += 256)
        ((float4*)sWr)[i] = ((const float4*)Wr)[i];
    __syncthreads();

    int warp = tid >> 5, lane = tid & 31;
    int t = blockIdx.x * 8 + warp;

    float acc[NE];
#pragma unroll
    for (int e = 0; e < NE; e++) acc[e] = 0.f;

    const float* xr = x + (size_t)t * Hd;
    for (int j = lane; j < Hd; j += 32) {
        float xv = xr[j];
#pragma unroll
        for (int e = 0; e < NE; e++) acc[e] += xv * sWr[j * NE + e];
    }
#pragma unroll
    for (int o = 16; o; o >>= 1)
#pragma unroll
        for (int e = 0; e < NE; e++)
            acc[e] += __shfl_xor_sync(0xffffffffu, acc[e], o);

    if (lane == 0) {
        float mx = acc[0];
#pragma unroll
        for (int e = 1; e < NE; e++) mx = fmaxf(mx, acc[e]);
        float pe[NE], s = 0.f;
#pragma unroll
        for (int e = 0; e < NE; e++) { pe[e] = expf(acc[e] - mx); s += pe[e]; }
        float inv = 1.f / s;
#pragma unroll
        for (int e = 0; e < NE; e++) { pe[e] *= inv; atomicAdd(&s_imp[e], pe[e]); }
        int e0 = 0;
#pragma unroll
        for (int e = 1; e < NE; e++) if (pe[e] > pe[e0]) e0 = e;
        int e1 = (e0 == 0) ? 1 : 0;
#pragma unroll
        for (int e = 0; e < NE; e++)
            if (e != e0 && e != e1 && pe[e] > pe[e1]) e1 = e;
        atomicAdd(&s_load[e0], 1);
        atomicAdd(&s_load[e1], 1);
        float ps = pe[e0] + pe[e1];
        g_fe[2 * t]     = e0;
        g_fe[2 * t + 1] = e1;
        g_fp[2 * t]     = pe[e0] / ps;
        g_fp[2 * t + 1] = pe[e1] / ps;
    }
    __syncthreads();
    if (tid < NE) {
        atomicAdd(&g_imp[tid], s_imp[tid]);
        atomicAdd(&g_load[tid], s_load[tid]);
    }
}

// ---------------- group slots by expert: packed keys -------------------------
__global__ void build_lists() {
    int n = blockIdx.x * 256 + threadIdx.x;
    if (n >= NSLOT) return;
    int e = g_fe[n];
    int i = atomicAdd(&g_cnt[e], 1);
    unsigned long long key =
        ((unsigned long long)__float_as_uint(g_fp[n]) << 32) |
        (unsigned int)(NSLOT - 1 - n);
    g_keys[e * NSLOT + i] = key;
}

__global__ void finalize_kernel() {
    int e = threadIdx.x;
    if (e < NE) g_active[e] = min(g_cnt[e], CAP);
}

// ---------------- rank: smem-tiled exact descending rank ---------------------
__global__ void rank_kernel() {
    int e = blockIdx.y;
    int c = g_cnt[e];
    int base = blockIdx.x * 256;
    if (base >= c) return;
    __shared__ unsigned long long sk[512];
    int tid = threadIdx.x;
    int idx = base + tid;
    bool act = idx < c;
    unsigned long long key = 0;
    if (act) key = g_keys[e * NSLOT + idx];
    int r = 0;
    for (int chunk = 0; chunk < c; chunk += 512) {
        int m = min(512, c - chunk);
        for (int i = tid; i < m; i += 256)
            sk[i] = g_keys[e * NSLOT + chunk + i];
        __syncthreads();
        if (act)
            for (int i = 0; i < m; i++)
                if (sk[i] > key) r++;
        __syncthreads();
    }
    if (act) {
        int n = NSLOT - 1 - (int)(unsigned int)(key & 0xFFFFFFFFu);
        float p = __uint_as_float((unsigned int)(key >> 32));
        bool keep = r < CAP;
        g_pos[n] = keep ? r : (CAP - 1);
        g_w[n]   = keep ? p : 0.f;
    }
}

// ---------------- dispatch: gather + split x into bf16 hi/lo planes ----------
__global__ void scatter_kernel(const float* __restrict__ x) {
    int n = blockIdx.x;
    float w = g_w[n];
    if (w == 0.f) return;
    int e = g_fe[n], pos = g_pos[n];
    int t = n >> 1;
    const float4* src = (const float4*)(x + (size_t)t * Hd);
    int tid = threadIdx.x;
    float4 a = src[2 * tid], b = src[2 * tid + 1];
    uint32_t h0, l0, h1, l1, h2, l2, h3, l3;
    split2(a.x, a.y, h0, l0);
    split2(a.z, a.w, h1, l1);
    split2(b.x, b.y, h2, l2);
    split2(b.z, b.w, h3, l3);
    size_t ub = ((size_t)e * CAP + pos) * (Hd / 8) + tid;
    g_xhi4[ub] = make_uint4(h0, h1, h2, h3);
    g_xlo4[ub] = make_uint4(l0, l1, l2, l3);
}

// ---------------- weight split: destinations resolved IN DEVICE CODE ---------
__global__ void wsplit_kernel(const float* __restrict__ W, int which) {
    uint4* hi;
    uint4* lo;
    if (which == 0)      { hi = g_wghi4; lo = g_wglo4; }
    else if (which == 1) { hi = g_wuhi4; lo = g_wulo4; }
    else                 { hi = g_w2hi4; lo = g_w2lo4; }
    size_t idx = (size_t)blockIdx.x * 256 + threadIdx.x;
    const float4* Wv = (const float4*)W;
    float4 a = Wv[2 * idx], b = Wv[2 * idx + 1];
    uint32_t h0, l0, h1, l1, h2, l2, h3, l3;
    split2(a.x, a.y, h0, l0);
    split2(a.z, a.w, h1, l1);
    split2(b.x, b.y, h2, l2);
    split2(b.z, b.w, h3, l3);
    hi[idx] = make_uint4(h0, h1, h2, h3);
    lo[idx] = make_uint4(l0, l1, l2, l3);
}

// ================= bf16x3 tensor-core grouped GEMM ===========================
// Round-14 proven structure: block 128x128x32, 8 warps (4x2), warp tile 32x64,
// two barriers per k-tile, register-staged LDG -> STS loader.
// ALL operands now pre-split bf16 hi/lo planes: staging is pure uint4 copy,
// zero split math in the mainloop.

#define SA_STRIDE 40
#define SB_STRIDE 136
#define A_BYTES   10240   // 128 * 80
#define B_BYTES   8704    // 32 * 272
#define BUF_BYTES 37888
#define SMEM_GEMM 75776

__device__ __forceinline__ void ldsm4(uint32_t* r, uint32_t addr) {
    asm volatile("ldmatrix.sync.aligned.m8n8.x4.shared.b16 {%0,%1,%2,%3}, [%4];"
        : "=r"(r[0]), "=r"(r[1]), "=r"(r[2]), "=r"(r[3]) : "r"(addr));
}
__device__ __forceinline__ void ldsm4t(uint32_t* r, uint32_t addr) {
    asm volatile("ldmatrix.sync.aligned.m8n8.x4.trans.shared.b16 {%0,%1,%2,%3}, [%4];"
        : "=r"(r[0]), "=r"(r[1]), "=r"(r[2]), "=r"(r[3]) : "r"(addr));
}
__device__ __forceinline__ void mma16816(float* d, const uint32_t* a, uint32_t b0, uint32_t b1) {
    asm volatile("mma.sync.aligned.m16n8k16.row.col.f32.bf16.bf16.f32 "
        "{%0,%1,%2,%3}, {%4,%5,%6,%7}, {%8,%9}, {%0,%1,%2,%3};"
        : "+f"(d[0]), "+f"(d[1]), "+f"(d[2]), "+f"(d[3])
        : "r"(a[0]), "r"(a[1]), "r"(a[2]), "r"(a[3]), "r"(b0), "r"(b1));
}

// ---- FUSED gate+up GEMM ------------------------------------------------------
// col0 = blockIdx.x * 64 covers 64 cols of BOTH Wg and Wu. Smem B cols [0,64)
// <- Wg planes, [64,128) <- Wu planes. Warps wn=0 gate, wn=1 up. Epilogue
// computes h = silu(g)*u once and writes bf16 hi/lo planes.
__global__ __launch_bounds__(256, 1) void mma_fused() {
    const int K = Hd, NW = Fd;
    int e = blockIdx.z;
    int row0 = blockIdx.y * 128;
    if (row0 >= g_active[e]) return;
    int col0 = blockIdx.x * 64;

    extern __shared__ char smem[];
    uint32_t sbase = (uint32_t)__cvta_generic_to_shared(smem);

    int tid  = threadIdx.x;
    int lane = tid & 31, wid = tid >> 5;
    int wm = wid >> 1, wn = wid & 1;

    int arow = tid >> 1, acol = (tid & 1) * 16;
    int brow = tid >> 3, bsub = tid & 7;
    int bcol = bsub * 16;
    int gcol = col0 + (bcol & 63);

    const __nv_bfloat16* Agh = (const __nv_bfloat16*)g_xhi4
        + ((size_t)e * CAP + row0 + arow) * K + acol;
    const __nv_bfloat16* Agl = (const __nv_bfloat16*)g_xlo4
        + ((size_t)e * CAP + row0 + arow) * K + acol;
    const __nv_bfloat16* Bgh = (const __nv_bfloat16*)(bsub < 4 ? g_wghi4 : g_wuhi4)
        + (size_t)e * K * NW + (size_t)brow * NW + gcol;
    const __nv_bfloat16* Bgl = (const __nv_bfloat16*)(bsub < 4 ? g_wglo4 : g_wulo4)
        + (size_t)e * K * NW + (size_t)brow * NW + gcol;

    uint4 arh[2], arl[2], brh[2], brl[2];
    arh[0] = *(const uint4*)Agh;  arh[1] = *(const uint4*)(Agh + 8);
    arl[0] = *(const uint4*)Agl;  arl[1] = *(const uint4*)(Agl + 8);
    brh[0] = *(const uint4*)Bgh;  brh[1] = *(const uint4*)(Bgh + 8);
    brl[0] = *(const uint4*)Bgl;  brl[1] = *(const uint4*)(Bgl + 8);

    float acc[2][8][4];
#pragma unroll
    for (int mi = 0; mi < 2; mi++)
#pragma unroll
        for (int ni = 0; ni < 8; ni++)
#pragma unroll
            for (int k = 0; k < 4; k++) acc[mi][ni][k] = 0.f;

    int offA = arow * 80 + acol * 2;
    int offB = brow * 272 + bcol * 2;
    int kTiles = K >> 5;
    for (int kt = 0; kt < kTiles; ++kt) {
        int cur = kt & 1;
        char* bufp = smem + cur * BUF_BYTES;

        // pure uint4 copy of pre-split planes
        *(uint4*)(bufp + offA)                              = arh[0];
        *(uint4*)(bufp + offA + 16)                         = arh[1];
        *(uint4*)(bufp + A_BYTES + offA)                    = arl[0];
        *(uint4*)(bufp + A_BYTES + offA + 16)               = arl[1];
        *(uint4*)(bufp + 2 * A_BYTES + offB)                = brh[0];
        *(uint4*)(bufp + 2 * A_BYTES + offB + 16)           = brh[1];
        *(uint4*)(bufp + 2 * A_BYTES + B_BYTES + offB)      = brl[0];
        *(uint4*)(bufp + 2 * A_BYTES + B_BYTES + offB + 16) = brl[1];
        __syncthreads();

        if (kt + 1 < kTiles) {
            Agh += 32; Agl += 32;
            Bgh += (size_t)32 * NW; Bgl += (size_t)32 * NW;
            arh[0] = *(const uint4*)Agh;  arh[1] = *(const uint4*)(Agh + 8);
            arl[0] = *(const uint4*)Agl;  arl[1] = *(const uint4*)(Agl + 8);
            brh[0] = *(const uint4*)Bgh;  brh[1] = *(const uint4*)(Bgh + 8);
            brl[0] = *(const uint4*)Bgl;  brl[1] = *(const uint4*)(Bgl + 8);
        }

        uint32_t sA = sbase + cur * BUF_BYTES;
        uint32_t sB = sA + 2 * A_BYTES;
#pragma unroll
        for (int ks = 0; ks < 2; ks++) {
            uint32_t ah[2][4], al[2][4], bh[4][4], bl[4][4];
#pragma unroll
            for (int mi = 0; mi < 2; mi++) {
                uint32_t r = wm * 32 + mi * 16 + (lane & 15);
                uint32_t c = ks * 16 + ((lane >> 4) << 3);
                uint32_t addr = sA + (r * SA_STRIDE + c) * 2;
                ldsm4(ah[mi], addr);
                ldsm4(al[mi], addr + A_BYTES);
            }
#pragma unroll
            for (int nb = 0; nb < 4; nb++) {
                uint32_t r = ks * 16 + (lane & 15);
                uint32_t c = wn * 64 + nb * 16 + ((lane >> 4) << 3);
                uint32_t addr = sB + (r * SB_STRIDE + c) * 2;
                ldsm4t(bh[nb], addr);
                ldsm4t(bl[nb], addr + B_BYTES);
            }
#pragma unroll
            for (int mi = 0; mi < 2; mi++)
#pragma unroll
                for (int nb = 0; nb < 4; nb++)
#pragma unroll
                    for (int j = 0; j < 2; j++) {
                        int ni = nb * 2 + j;
                        mma16816(acc[mi][ni], ah[mi], bh[nb][2 * j], bh[nb][2 * j + 1]);
                        mma16816(acc[mi][ni], ah[mi], bl[nb][2 * j], bl[nb][2 * j + 1]);
                        mma16816(acc[mi][ni], al[mi], bh[nb][2 * j], bh[nb][2 * j + 1]);
                    }
        }
        __syncthreads();
    }

    // ---- fused epilogue: up warps -> smem, gate warps compute h -> planes ----
    float* su = (float*)smem;
    int gq = lane >> 2, q = lane & 3;
    if (wn == 1) {
#pragma unroll
        for (int mi = 0; mi < 2; mi++) {
            int rl = wm * 32 + mi * 16 + gq;
#pragma unroll
            for (int ni = 0; ni < 8; ni++) {
                int c = ni * 8 + q * 2;
                su[rl * 64 + c]           = acc[mi][ni][0];
                su[rl * 64 + c + 1]       = acc[mi][ni][1];
                su[(rl + 8) * 64 + c]     = acc[mi][ni][2];
                su[(rl + 8) * 64 + c + 1] = acc[mi][ni][3];
            }
        }
    }
    __syncthreads();
    if (wn == 0) {
        __nv_bfloat16* HH = (__nv_bfloat16*)g_hhi4 + (size_t)e * CAP * Fd;
        __nv_bfloat16* HL = (__nv_bfloat16*)g_hlo4 + (size_t)e * CAP * Fd;
#pragma unroll
        for (int mi = 0; mi < 2; mi++) {
            int rl = wm * 32 + mi * 16 + gq;
#pragma unroll
            for (int ni = 0; ni < 8; ni++) {
                int c = ni * 8 + q * 2;
                float u00 = su[rl * 64 + c];
                float u01 = su[rl * 64 + c + 1];
                float u10 = su[(rl + 8) * 64 + c];
                float u11 = su[(rl + 8) * 64 + c + 1];
                float g00 = acc[mi][ni][0], g01 = acc[mi][ni][1];
                float g10 = acc[mi][ni][2], g11 = acc[mi][ni][3];
                float h00 = g00 / (1.f + expf(-g00)) * u00;
                float h01 = g01 / (1.f + expf(-g01)) * u01;
                float h10 = g10 / (1.f + expf(-g10)) * u10;
                float h11 = g11 / (1.f + expf(-g11)) * u11;
                uint32_t hp0, lp0, hp1, lp1;
                split2(h00, h01, hp0, lp0);
                split2(h10, h11, hp1, lp1);
                size_t i0 = (size_t)(row0 + rl) * Fd + col0 + c;
                size_t i1 = i0 + (size_t)8 * Fd;
                *(uint32_t*)&HH[i0] = hp0;
                *(uint32_t*)&HL[i0] = lp0;
                *(uint32_t*)&HH[i1] = hp1;
                *(uint32_t*)&HL[i1] = lp1;
            }
        }
    }
}

// ---- down GEMM: y = h @ W2, all pre-split planes -----------------------------
__global__ __launch_bounds__(256, 1) void mma_down() {
    const int K = Fd, NW = Hd;
    int e = blockIdx.z;
    int row0 = blockIdx.y * 128;
    if (row0 >= g_active[e]) return;
    int col0 = blockIdx.x * 128;

    extern __shared__ char smem[];
    uint32_t sbase = (uint32_t)__cvta_generic_to_shared(smem);

    int tid  = threadIdx.x;
    int lane = tid & 31, wid = tid >> 5;
    int wm = wid >> 1, wn = wid & 1;

    int arow = tid >> 1, acol = (tid & 1) * 16;
    int brow = tid >> 3, bcol = (tid & 7) * 16;

    const __nv_bfloat16* Agh = (const __nv_bfloat16*)g_hhi4
        + ((size_t)e * CAP + row0 + arow) * K + acol;
    const __nv_bfloat16* Agl = (const __nv_bfloat16*)g_hlo4
        + ((size_t)e * CAP + row0 + arow) * K + acol;
    const __nv_bfloat16* Bgh = (const __nv_bfloat16*)g_w2hi4
        + (size_t)e * K * NW + (size_t)brow * NW + col0 + bcol;
    const __nv_bfloat16* Bgl = (const __nv_bfloat16*)g_w2lo4
        + (size_t)e * K * NW + (size_t)brow * NW + col0 + bcol;

    uint4 arh[2], arl[2], brh[2], brl[2];
    arh[0] = *(const uint4*)Agh;  arh[1] = *(const uint4*)(Agh + 8);
    arl[0] = *(const uint4*)Agl;  arl[1] = *(const uint4*)(Agl + 8);
    brh[0] = *(const uint4*)Bgh;  brh[1] = *(const uint4*)(Bgh + 8);
    brl[0] = *(const uint4*)Bgl;  brl[1] = *(const uint4*)(Bgl + 8);

    float acc[2][8][4];
#pragma unroll
    for (int mi = 0; mi < 2; mi++)
#pragma unroll
        for (int ni = 0; ni < 8; ni++)
#pragma unroll
            for (int k = 0; k < 4; k++) acc[mi][ni][k] = 0.f;

    int offA = arow * 80 + acol * 2;
    int offB = brow * 272 + bcol * 2;
    int kTiles = K >> 5;
    for (int kt = 0; kt < kTiles; ++kt) {
        int cur = kt & 1;
        char* bufp = smem + cur * BUF_BYTES;

        *(uint4*)(bufp + offA)                              = arh[0];
        *(uint4*)(bufp + offA + 16)                         = arh[1];
        *(uint4*)(bufp + A_BYTES + offA)                    = arl[0];
        *(uint4*)(bufp + A_BYTES + offA + 16)               = arl[1];
        *(uint4*)(bufp + 2 * A_BYTES + offB)                = brh[0];
        *(uint4*)(bufp + 2 * A_BYTES + offB + 16)           = brh[1];
        *(uint4*)(bufp + 2 * A_BYTES + B_BYTES + offB)      = brl[0];
        *(uint4*)(bufp + 2 * A_BYTES + B_BYTES + offB + 16) = brl[1];
        __syncthreads();

        if (kt + 1 < kTiles) {
            Agh += 32; Agl += 32;
            Bgh += (size_t)32 * NW; Bgl += (size_t)32 * NW;
            arh[0] = *(const uint4*)Agh;  arh[1] = *(const uint4*)(Agh + 8);
            arl[0] = *(const uint4*)Agl;  arl[1] = *(const uint4*)(Agl + 8);
            brh[0] = *(const uint4*)Bgh;  brh[1] = *(const uint4*)(Bgh + 8);
            brl[0] = *(const uint4*)Bgl;  brl[1] = *(const uint4*)(Bgl + 8);
        }

        uint32_t sA = sbase + cur * BUF_BYTES;
        uint32_t sB = sA + 2 * A_BYTES;
#pragma unroll
        for (int ks = 0; ks < 2; ks++) {
            uint32_t ah[2][4], al[2][4], bh[4][4], bl[4][4];
#pragma unroll
            for (int mi = 0; mi < 2; mi++) {
                uint32_t r = wm * 32 + mi * 16 + (lane & 15);
                uint32_t c = ks * 16 + ((lane >> 4) << 3);
                uint32_t addr = sA + (r * SA_STRIDE + c) * 2;
                ldsm4(ah[mi], addr);
                ldsm4(al[mi], addr + A_BYTES);
            }
#pragma unroll
            for (int nb = 0; nb < 4; nb++) {
                uint32_t r = ks * 16 + (lane & 15);
                uint32_t c = wn * 64 + nb * 16 + ((lane >> 4) << 3);
                uint32_t addr = sB + (r * SB_STRIDE + c) * 2;
                ldsm4t(bh[nb], addr);
                ldsm4t(bl[nb], addr + B_BYTES);
            }
#pragma unroll
            for (int mi = 0; mi < 2; mi++)
#pragma unroll
                for (int nb = 0; nb < 4; nb++)
#pragma unroll
                    for (int j = 0; j < 2; j++) {
                        int ni = nb * 2 + j;
                        mma16816(acc[mi][ni], ah[mi], bh[nb][2 * j], bh[nb][2 * j + 1]);
                        mma16816(acc[mi][ni], ah[mi], bl[nb][2 * j], bl[nb][2 * j + 1]);
                        mma16816(acc[mi][ni], al[mi], bh[nb][2 * j], bh[nb][2 * j + 1]);
                    }
        }
        __syncthreads();
    }

    float* C = g_y + (size_t)e * CAP * NW;
    int gq = lane >> 2, q = lane & 3;
#pragma unroll
    for (int mi = 0; mi < 2; mi++) {
        int r = row0 + wm * 32 + mi * 16 + gq;
#pragma unroll
        for (int ni = 0; ni < 8; ni++) {
            int c = col0 + wn * 64 + ni * 8 + q * 2;
            size_t i0 = (size_t)r * NW + c;
            size_t i1 = i0 + (size_t)8 * NW;
            *(float2*)&C[i0] = make_float2(acc[mi][ni][0], acc[mi][ni][1]);
            *(float2*)&C[i1] = make_float2(acc[mi][ni][2], acc[mi][ni][3]);
        }
    }
}

// ---------------- combine ----------------------------------------------------
__global__ void combine_kernel(float* __restrict__ out) {
    int t = blockIdx.x;
    int tid = threadIdx.x;
    int n0 = 2 * t, n1 = 2 * t + 1;
    float w0 = g_w[n0], w1 = g_w[n1];
    const float4* y0 = (const float4*)(g_y + ((size_t)g_fe[n0] * CAP + g_pos[n0]) * Hd);
    const float4* y1 = (const float4*)(g_y + ((size_t)g_fe[n1] * CAP + g_pos[n1]) * Hd);
    float4 a = y0[tid], b = y1[tid];
    float4 o;
    o.x = w0 * a.x + w1 * b.x;
    o.y = w0 * a.y + w1 * b.y;
    o.z = w0 * a.z + w1 * b.z;
    o.w = w0 * a.w + w1 * b.w;
    ((float4*)(out + (size_t)t * Hd))[tid] = o;
}

// ---------------- aux loss -----------------------------------------------------
__global__ void aux_kernel(float* __restrict__ out, int out_size) {
    if (threadIdx.x == 0) {
        float s = 0.f;
#pragma unroll
        for (int e = 0; e < NE; e++) s += g_imp[e] * (float)g_load[e];
        float aux = (float)NE * s / (float)(Tt * 2);
        if (out_size > Tt * Hd) out[(size_t)Tt * Hd] = aux;
    }
}

// ---------------- launch -------------------------------------------------------
extern "C" void kernel_launch(void* const* d_in, const int* in_sizes, int n_in,
                              void* d_out, int out_size) {
    const float* x  = (const float*)d_in[0];
    const float* Wr = (const float*)d_in[1];
    const float* Wg = (const float*)d_in[2];
    const float* Wu = (const float*)d_in[3];
    const float* W2 = (const float*)d_in[4];
    float* out = (float*)d_out;

    int smem_bytes = SMEM_GEMM;
    cudaFuncSetAttribute(mma_fused, cudaFuncAttributeMaxDynamicSharedMemorySize, smem_bytes);
    cudaFuncSetAttribute(mma_down,  cudaFuncAttributeMaxDynamicSharedMemorySize, smem_bytes);

    zero_kernel<<<1, 32>>>();
    router_kernel<<<Tt / 8, 256>>>(x, Wr);
    build_lists<<<NSLOT / 256, 256>>>();
    finalize_kernel<<<1, 32>>>();
    rank_kernel<<<dim3(NSLOT / 256, NE), 256>>>();
    scatter_kernel<<<NSLOT, 128>>>(x);

    int wblk = (NE * Hd * Fd) / (256 * 8);
    wsplit_kernel<<<wblk, 256>>>(Wg, 0);
    wsplit_kernel<<<wblk, 256>>>(Wu, 1);
    wsplit_kernel<<<wblk, 256>>>(W2, 2);

    dim3 grid_fused(Fd / 64, CAP / 128, NE);   // 32 x 40 x 8
    dim3 grid_down (Hd / 128, CAP / 128, NE);  //  8 x 40 x 8

    mma_fused<<<grid_fused, 256, smem_bytes>>>();  // h = silu(x@Wg)*(x@Wu)
    mma_down <<<grid_down, 256, smem_bytes>>>();   // y = h @ W2

    combine_kernel<<<Tt, 256>>>(out);
    aux_kernel<<<1, 32>>>(out, out_size);
}